// round 16
// baseline (speedup 1.0000x reference)
#include <cuda_runtime.h>

// LieTransport bilinear backward warp — binned tiles + SMEM halos, v2.
// Fixes vs R15: (1) conflict-free smem channel stride (CH_F4=340: 4*340 ≡ 16
// mod 32 -> adjacent channels in an 8-lane phase cover disjoint bank halves,
// every tap LDS.128 at the 4-cyc crossbar floor); (2) chunked gather grid for
// load balance (border tiles collect ~10x mean records from clamping);
// (3) software-pipelined record fetch.

#define Hd 128
#define Wd 128
#define Cd 64
#define HWd (Hd * Wd)
#define NPIX (4 * HWd)
#define NTILE 1024                 // 4 batches x 16x16 tiles
#define CAP 2048
#define CHUNK 128
#define NCHUNK (CAP / CHUNK)       // 16

#define ROW_F4 37                  // 9 px * 4 quarters + 1 pad
#define CH_F4  340                 // >= 9*37, and ≡ 4 (mod 8) -> conflict-free
#define SM_F4  (8 * CH_F4)         // 2720 float4 = 43,520 B

__device__ unsigned g_cnt[NTILE];
__device__ unsigned g_ovfn;
__device__ uint4    g_rec[NTILE * CAP];
__device__ uint4    g_ovf[NPIX];

// ---- K0: zero counters ----
__global__ void k_zero()
{
    g_cnt[threadIdx.x] = 0u;
    if (threadIdx.x == 0) g_ovfn = 0u;
}

// ---- K1: bin pixels by tap tile ----
__global__ __launch_bounds__(256) void k_bin(
    const float* __restrict__ flow, const float* __restrict__ dt)
{
    const int pid = blockIdx.x * 256 + threadIdx.x;
    const int b = pid >> 14;
    const int y = (pid >> 7) & (Hd - 1);
    const int x = pid & (Wd - 1);

    const float d   = dt[b];
    const float d64 = d * 64.0f;
    const int   fb  = ((b * 2) * Hd + y) * Wd + x;
    const float fx  = flow[fb];
    const float fy  = flow[fb + HWd];

    const float ix = fminf(fmaxf(
        fmaf((float)x, 128.0f / 127.0f, fmaf(-fx, d64, -0.5f)), 0.0f), 127.0f);
    const float iy = fminf(fmaxf(
        fmaf((float)y, 128.0f / 127.0f, fmaf(-fy, d64, -0.5f)), 0.0f), 127.0f);

    const float x0f = floorf(ix);
    const float y0f = floorf(iy);

    const int x0 = (int)x0f;
    const int y0 = (int)y0f;
    const int tile = b * 256 + (y0 >> 3) * 16 + (x0 >> 3);

    uint4 rec;
    rec.x = (unsigned)x | ((unsigned)y << 7) | ((unsigned)x0 << 14) | ((unsigned)y0 << 21);
    rec.y = (unsigned)tile;
    rec.z = __float_as_uint(ix - x0f);
    rec.w = __float_as_uint(iy - y0f);

    const unsigned rank = atomicAdd(&g_cnt[tile], 1u);
    if (rank < CAP) {
        g_rec[tile * CAP + rank] = rec;
    } else {
        const unsigned o = atomicAdd(&g_ovfn, 1u);
        g_ovf[o] = rec;
    }
}

// ---- K2: staged gather. Block = (tile, chunk, 8-channel group). ----
__global__ __launch_bounds__(256) void k_gather(
    const float4* __restrict__ h4, float4* __restrict__ out4)
{
    __shared__ float4 s[SM_F4];

    const int tile = blockIdx.x;
    const int cg   = blockIdx.y;            // 0..7 -> channels cg*8..cg*8+7
    const int ck   = blockIdx.z;            // record chunk

    const unsigned n  = min(g_cnt[tile], (unsigned)CAP);
    const unsigned c0 = (unsigned)(ck * CHUNK);
    if (c0 >= n) return;                    // empty chunk: cheap exit
    const unsigned c1 = min(c0 + (unsigned)CHUNK, n);

    const int b  = tile >> 8;
    const int ty = ((tile >> 4) & 15) * 8;
    const int tx = (tile & 15) * 8;
    const int tid = threadIdx.x;
    const int ch0 = cg * 8;

    // ---- stage halo: 8 ch x 9 rows x 36 float4 (coalesced, once) ----
    for (int idx = tid; idx < 8 * 9 * 36; idx += 256) {
        const int i    = idx % 36;           // px*4 + q within row
        const int task = idx / 36;
        const int u    = task / 9;           // channel sub 0..7
        const int r    = task % 9;           // halo row
        const int px   = i >> 2;
        const int q    = i & 3;
        const int gy   = min(ty + r,  127);
        const int gx   = min(tx + px, 127);
        const int plane = (b * Cd + ch0 + u) * HWd;
        s[u * CH_F4 + r * ROW_F4 + i] = __ldg(h4 + (plane + gy * Wd + gx) * 4 + q);
    }
    __syncthreads();

    // ---- sample records from smem (conflict-free; pipelined rec fetch) ----
    const int w    = tid >> 5;
    const int lane = tid & 31;
    const int u    = lane >> 2;              // channel sub 0..7
    const int q    = lane & 3;               // float4 quarter
    const int plane = (b * Cd + ch0 + u) * HWd;
    const int sbase = u * CH_F4;

    unsigned i = c0 + (unsigned)w;
    if (i >= c1) return;

    uint4 rec = g_rec[tile * CAP + i];
    while (true) {
        const unsigned nx = i + 8;
        uint4 nrec;
        const bool have = nx < c1;
        if (have) nrec = g_rec[tile * CAP + nx];

        const int x  = rec.x & 127;
        const int y  = (rec.x >> 7) & 127;
        const int x0 = (rec.x >> 14) & 127;
        const int y0 = (rec.x >> 21) & 127;
        const float wx = __uint_as_float(rec.z);
        const float wy = __uint_as_float(rec.w);

        const int px0 = x0 - tx;
        const int py0 = y0 - ty;
        const int px1 = min(x0 + 1, 127) - tx;
        const int py1 = min(y0 + 1, 127) - ty;

        const float4 v00 = s[sbase + py0 * ROW_F4 + px0 * 4 + q];
        const float4 v01 = s[sbase + py0 * ROW_F4 + px1 * 4 + q];
        const float4 v10 = s[sbase + py1 * ROW_F4 + px0 * 4 + q];
        const float4 v11 = s[sbase + py1 * ROW_F4 + px1 * 4 + q];

        float4 top, bot, r;
        top.x = fmaf(wx, v01.x - v00.x, v00.x);
        top.y = fmaf(wx, v01.y - v00.y, v00.y);
        top.z = fmaf(wx, v01.z - v00.z, v00.z);
        top.w = fmaf(wx, v01.w - v00.w, v00.w);
        bot.x = fmaf(wx, v11.x - v10.x, v10.x);
        bot.y = fmaf(wx, v11.y - v10.y, v10.y);
        bot.z = fmaf(wx, v11.z - v10.z, v10.z);
        bot.w = fmaf(wx, v11.w - v10.w, v10.w);
        r.x = fmaf(wy, bot.x - top.x, top.x);
        r.y = fmaf(wy, bot.y - top.y, top.y);
        r.z = fmaf(wy, bot.z - top.z, top.z);
        r.w = fmaf(wy, bot.w - top.w, top.w);

        __stcs(out4 + (plane + y * Wd + x) * 4 + q, r);

        if (!have) break;
        rec = nrec;
        i = nx;
    }
}

// ---- K3: overflow backstop, thread per (record, channel, quarter) ----
__global__ __launch_bounds__(256) void k_overflow(
    const float4* __restrict__ h4, float4* __restrict__ out4)
{
    const unsigned n = g_ovfn;
    if (n == 0) return;
    const unsigned total  = n * Cd * 4;
    const unsigned stride = gridDim.x * 256;
    for (unsigned idx = blockIdx.x * 256 + threadIdx.x; idx < total; idx += stride) {
        const uint4 rec = g_ovf[idx / (Cd * 4)];
        const int rem = idx & (Cd * 4 - 1);
        const int ch  = rem >> 2;
        const int q   = rem & 3;

        const int b  = (int)(rec.y >> 8);
        const int x  = rec.x & 127;
        const int y  = (rec.x >> 7) & 127;
        const int x0 = (rec.x >> 14) & 127;
        const int y0 = (rec.x >> 21) & 127;
        const float wx = __uint_as_float(rec.z);
        const float wy = __uint_as_float(rec.w);
        const int x1 = min(x0 + 1, 127);
        const int y1 = min(y0 + 1, 127);

        const int plane = (b * Cd + ch) * HWd;
        const float4 v00 = __ldg(h4 + (plane + y0 * Wd + x0) * 4 + q);
        const float4 v01 = __ldg(h4 + (plane + y0 * Wd + x1) * 4 + q);
        const float4 v10 = __ldg(h4 + (plane + y1 * Wd + x0) * 4 + q);
        const float4 v11 = __ldg(h4 + (plane + y1 * Wd + x1) * 4 + q);

        float4 top, bot, r;
        top.x = fmaf(wx, v01.x - v00.x, v00.x);
        top.y = fmaf(wx, v01.y - v00.y, v00.y);
        top.z = fmaf(wx, v01.z - v00.z, v00.z);
        top.w = fmaf(wx, v01.w - v00.w, v00.w);
        bot.x = fmaf(wx, v11.x - v10.x, v10.x);
        bot.y = fmaf(wx, v11.y - v10.y, v10.y);
        bot.z = fmaf(wx, v11.z - v10.z, v10.z);
        bot.w = fmaf(wx, v11.w - v10.w, v10.w);
        r.x = fmaf(wy, bot.x - top.x, top.x);
        r.y = fmaf(wy, bot.y - top.y, top.y);
        r.z = fmaf(wy, bot.z - top.z, top.z);
        r.w = fmaf(wy, bot.w - top.w, top.w);

        out4[(plane + y * Wd + x) * 4 + q] = r;
    }
}

extern "C" void kernel_launch(void* const* d_in, const int* in_sizes, int n_in,
                              void* d_out, int out_size)
{
    const float* h_prev = (const float*)d_in[0];
    const float* flow   = (const float*)d_in[1];
    const float* dt     = (const float*)d_in[2];
    float* out          = (float*)d_out;

    k_zero<<<1, NTILE>>>();
    k_bin<<<NPIX / 256, 256>>>(flow, dt);

    dim3 grid(NTILE, 8, NCHUNK);   // tiles x channel groups x record chunks
    k_gather<<<grid, 256>>>((const float4*)h_prev, (float4*)out);
    k_overflow<<<128, 256>>>((const float4*)h_prev, (float4*)out);
}